// round 17
// baseline (speedup 1.0000x reference)
#include <cuda_runtime.h>
#include <cuda_bf16.h>
#include <cuda_fp16.h>
#include <cstdint>

// ---------------- problem constants ----------------
#define BATCH  2
#define SEQ    4096
#define DMODEL 1024
#define DINNER 2048
#define DSTATE 128
#define NHEADS 32
#define HDIM   64
#define CDIM   2304        // DINNER + 2*DSTATE
#define NIN    4384        // 2*DINNER + 2*DSTATE + NHEADS
#define QC     64          // chunk length
#define NCH    64          // SEQ / QC
#define BL     8192        // BATCH * SEQ
#define DTMIN  0.001f
#define DTMAX  0.1f

// ---------------- scratch (device globals; no allocs allowed) ----------------
__device__ __half g_zx_h[(size_t)BL * NIN];        // in_proj output (fp16)
__device__ __half g_xbc_h[(size_t)BL * CDIM];      // conv+silu output (fp16)
__device__ float g_dt[(size_t)BL * NHEADS];        // dt after sigmoid mapping (fp32-exact)
__device__ float g_Acum[(size_t)BATCH * NCH * NHEADS * QC];
__device__ float g_cdecay[(size_t)BATCH * NCH * NHEADS];
__device__ __half g_CB_h[(size_t)BATCH * NCH * QC * QC];   // head-independent C.B (fp16)
__device__ __half g_states_h[(size_t)BATCH * NCH * NHEADS * HDIM * DSTATE];
__device__ __half g_prevs_h [(size_t)BATCH * NCH * NHEADS * HDIM * DSTATE];
__device__ float g_Y[(size_t)BL * DINNER];         // Yd then += Yo + skip
__device__ float g_out[(size_t)BL * DMODEL];       // out_proj output (pre-LN)

// fp16 operands for tensor-core GEMMs
__device__ __half g_x_h [(size_t)BL * DMODEL];
__device__ __half g_w1_h[(size_t)NIN * DMODEL];
__device__ __half g_y_h [(size_t)BL * DINNER];
__device__ __half g_w2_h[(size_t)DMODEL * DINNER];

// ---------------- helpers ----------------
__device__ __forceinline__ float block_sum(float v) {
    __shared__ float sh[32];
    __syncthreads();
    int lane = threadIdx.x & 31, wid = threadIdx.x >> 5;
    #pragma unroll
    for (int o = 16; o > 0; o >>= 1) v += __shfl_xor_sync(0xffffffffu, v, o);
    if (lane == 0) sh[wid] = v;
    __syncthreads();
    float r = (threadIdx.x < (blockDim.x >> 5)) ? sh[threadIdx.x] : 0.f;
    if (wid == 0) {
        #pragma unroll
        for (int o = 16; o > 0; o >>= 1) r += __shfl_xor_sync(0xffffffffu, r, o);
        if (lane == 0) sh[0] = r;
    }
    __syncthreads();
    return sh[0];
}

__device__ __forceinline__ float silu(float x) { return x / (1.f + __expf(-x)); }

__device__ __forceinline__ uint32_t smem_u32(const void* p) {
    uint32_t a;
    asm("{ .reg .u64 t; cvta.to.shared.u64 t, %1; cvt.u32.u64 %0, t; }" : "=r"(a) : "l"(p));
    return a;
}

__device__ __forceinline__ void store2(float* C, size_t idx, float a, float b) {
    *(float2*)&C[idx] = make_float2(a, b);
}
__device__ __forceinline__ void store2(__half* C, size_t idx, float a, float b) {
    *(__half2*)&C[idx] = __floats2half2_rn(a, b);
}

// ---------------- portable async-copy / ldmatrix / mma wrappers ----------------
__device__ __forceinline__ void cp16(uint32_t dst, const void* src, bool pred) {
    int sz = pred ? 16 : 0;
    asm volatile("cp.async.cg.shared.global [%0], [%1], 16, %2;\n"
                 :: "r"(dst), "l"(src), "r"(sz) : "memory");
}
__device__ __forceinline__ void cp_commit() {
    asm volatile("cp.async.commit_group;" ::: "memory");
}
template <int N>
__device__ __forceinline__ void cp_wait() {
    asm volatile("cp.async.wait_group %0;" :: "n"(N) : "memory");
}
__device__ __forceinline__ void ldm_x4(uint32_t* r, uint32_t addr) {
    asm volatile("ldmatrix.sync.aligned.m8n8.x4.shared.b16 {%0,%1,%2,%3}, [%4];"
                 : "=r"(r[0]), "=r"(r[1]), "=r"(r[2]), "=r"(r[3]) : "r"(addr));
}
__device__ __forceinline__ void ldm_x2(uint32_t* r, uint32_t addr) {
    asm volatile("ldmatrix.sync.aligned.m8n8.x2.shared.b16 {%0,%1}, [%2];"
                 : "=r"(r[0]), "=r"(r[1]) : "r"(addr));
}
__device__ __forceinline__ void ldm_x4_t(uint32_t* r, uint32_t addr) {
    asm volatile("ldmatrix.sync.aligned.m8n8.x4.trans.shared.b16 {%0,%1,%2,%3}, [%4];"
                 : "=r"(r[0]), "=r"(r[1]), "=r"(r[2]), "=r"(r[3]) : "r"(addr));
}
__device__ __forceinline__ void ldm_x2_t(uint32_t* r, uint32_t addr) {
    asm volatile("ldmatrix.sync.aligned.m8n8.x2.trans.shared.b16 {%0,%1}, [%2];"
                 : "=r"(r[0]), "=r"(r[1]) : "r"(addr));
}
__device__ __forceinline__ void mma_f16(float* d, const uint32_t* a, const uint32_t* b) {
    asm volatile("mma.sync.aligned.m16n8k16.row.col.f32.f16.f16.f32 "
                 "{%0,%1,%2,%3}, {%4,%5,%6,%7}, {%8,%9}, {%0,%1,%2,%3};"
                 : "+f"(d[0]), "+f"(d[1]), "+f"(d[2]), "+f"(d[3])
                 : "r"(a[0]), "r"(a[1]), "r"(a[2]), "r"(a[3]), "r"(b[0]), "r"(b[1]));
}
__device__ __forceinline__ void mma_f16_2(float* d, const uint32_t* a, uint32_t b0, uint32_t b1) {
    asm volatile("mma.sync.aligned.m16n8k16.row.col.f32.f16.f16.f32 "
                 "{%0,%1,%2,%3}, {%4,%5,%6,%7}, {%8,%9}, {%0,%1,%2,%3};"
                 : "+f"(d[0]), "+f"(d[1]), "+f"(d[2]), "+f"(d[3])
                 : "r"(a[0]), "r"(a[1]), "r"(a[2]), "r"(a[3]), "r"(b0), "r"(b1));
}

// ---------------- fp32 -> fp16 convert ----------------
__global__ void k_cvt_h(const float* __restrict__ in, __half* __restrict__ out, long long n4) {
    long long i = (long long)blockIdx.x * blockDim.x + threadIdx.x;
    if (i >= n4) return;
    float4 v = ((const float4*)in)[i];
    ((__half2*)out)[i * 2 + 0] = __floats2half2_rn(v.x, v.y);
    ((__half2*)out)[i * 2 + 1] = __floats2half2_rn(v.z, v.w);
}

// ---------------- fp16 HMMA GEMM: C[M,N] = A[M,K] * B[N,K]^T, 3-stage pipeline --------
#define BKH    64
#define HS_STR 72
#define H_TILE (128 * HS_STR)
#define OFF_B  H_TILE
#define H_STAGE (2 * H_TILE)
#define H_STAGE_B (H_STAGE * 2)            // 36864 bytes
#define GEMMH_SMEM_BYTES (3 * H_STAGE_B)   // 110592

__device__ __forceinline__ void load_stage_h(
    const __half* __restrict__ A, const __half* __restrict__ B,
    uint32_t smbase, int stage, int m0, int n0, int k0, int N, int K, int tid)
{
    uint32_t sb = smbase + (uint32_t)stage * H_STAGE_B;
    #pragma unroll
    for (int j = 0; j < 4; j++) {
        int c = tid + j * 256;
        int r = c >> 3, c8 = (c & 7) * 8;
        uint32_t soff = (uint32_t)(r * HS_STR + c8) * 2;
        cp16(sb + soff, A + (size_t)(m0 + r) * K + k0 + c8, true);
        bool ok = (n0 + r) < N;
        cp16(sb + OFF_B * 2 + soff, B + (size_t)(ok ? (n0 + r) : 0) * K + k0 + c8, ok);
    }
}

template <typename OT>
__global__ void __launch_bounds__(256, 2)
k_gemm_h(const __half* __restrict__ A, const __half* __restrict__ B,
         OT* __restrict__ C, int M, int N, int K) {
    extern __shared__ __half smg[];
    const uint32_t smbase = smem_u32(smg);
    const int tid = threadIdx.x, wid = tid >> 5, lid = tid & 31;
    const int m0 = blockIdx.y * 128, n0 = blockIdx.x * 128;
    const int wm = (wid >> 2) * 64;
    const int wn = (wid & 3) * 32;
    const int l15 = lid & 15;

    float acc[4][4][4];
    #pragma unroll
    for (int mi = 0; mi < 4; mi++)
        #pragma unroll
        for (int ni = 0; ni < 4; ni++)
            #pragma unroll
            for (int k = 0; k < 4; k++) acc[mi][ni][k] = 0.f;

    const int la_row = wm + l15;
    const int la_col = (lid >> 4) * 8;
    const int lb_row = wn + l15;           // 16-row B ldm_x4

    const int NIT = K / BKH;
    load_stage_h(A, B, smbase, 0, m0, n0, 0, N, K, tid);
    cp_commit();
    load_stage_h(A, B, smbase, 1, m0, n0, BKH, N, K, tid);
    cp_commit();

    int stg = 0;
    for (int it = 0; it < NIT; it++) {
        if (it == NIT - 1) cp_wait<0>(); else cp_wait<1>();
        __syncthreads();

        uint32_t sb = smbase + (uint32_t)stg * H_STAGE_B;
        #pragma unroll
        for (int ks = 0; ks < 4; ks++) {
            uint32_t af[4][4], bq[2][4];
            #pragma unroll
            for (int mi = 0; mi < 4; mi++)
                ldm_x4(af[mi], sb + (uint32_t)((la_row + mi * 16) * HS_STR + ks * 16 + la_col) * 2);
            ldm_x4(bq[0], sb + (uint32_t)(OFF_B + (lb_row)      * HS_STR + ks * 16 + la_col) * 2);
            ldm_x4(bq[1], sb + (uint32_t)(OFF_B + (lb_row + 16) * HS_STR + ks * 16 + la_col) * 2);
            #pragma unroll
            for (int mi = 0; mi < 4; mi++) {
                mma_f16_2(acc[mi][0], af[mi], bq[0][0], bq[0][2]);
                mma_f16_2(acc[mi][1], af[mi], bq[0][1], bq[0][3]);
                mma_f16_2(acc[mi][2], af[mi], bq[1][0], bq[1][2]);
                mma_f16_2(acc[mi][3], af[mi], bq[1][1], bq[1][3]);
            }
        }
        if (it + 2 < NIT) {
            int ns = stg - 1; if (ns < 0) ns += 3;
            load_stage_h(A, B, smbase, ns, m0, n0, (it + 2) * BKH, N, K, tid);
            cp_commit();
        }
        stg++; if (stg == 3) stg = 0;
    }

    const int r0 = m0 + wm + (lid >> 2);
    const int c0 = n0 + wn + (lid & 3) * 2;
    #pragma unroll
    for (int mi = 0; mi < 4; mi++) {
        #pragma unroll
        for (int ni = 0; ni < 4; ni++) {
            int col = c0 + ni * 8;
            if (col < N) {
                int row = r0 + mi * 16;
                store2(C, (size_t)row * N + col, acc[mi][ni][0], acc[mi][ni][1]);
                store2(C, (size_t)(row + 8) * N + col, acc[mi][ni][2], acc[mi][ni][3]);
            }
        }
    }
}

// ---------------- fp32-exact dt ----------------
__global__ void k_dtfix(const float* __restrict__ x, const float* __restrict__ in_proj_w,
                        const float* __restrict__ dt_bias) {
    __shared__ float xs[64 * 64];
    __shared__ float ws[32 * 65];
    const int tid = threadIdx.x;
    const int h = tid & 31, rg = tid >> 5;
    const int bl0 = blockIdx.x * 64;
    const float* wdt = in_proj_w + (size_t)(DINNER + CDIM) * DMODEL;

    float acc[8];
    #pragma unroll
    for (int i = 0; i < 8; i++) acc[i] = 0.f;

    for (int k0 = 0; k0 < DMODEL; k0 += 64) {
        __syncthreads();
        #pragma unroll
        for (int it = 0; it < 4; it++) {
            int i4 = tid + it * 256;
            int r = i4 >> 4, c4 = (i4 & 15) * 4;
            *(float4*)&xs[r * 64 + c4] = *(const float4*)&x[(size_t)(bl0 + r) * DMODEL + k0 + c4];
        }
        #pragma unroll
        for (int it = 0; it < 2; it++) {
            int i4 = tid + it * 256;
            int r = i4 >> 4, c4 = (i4 & 15) * 4;
            float4 v = *(const float4*)&wdt[(size_t)r * DMODEL + k0 + c4];
            ws[r * 65 + c4 + 0] = v.x; ws[r * 65 + c4 + 1] = v.y;
            ws[r * 65 + c4 + 2] = v.z; ws[r * 65 + c4 + 3] = v.w;
        }
        __syncthreads();
        #pragma unroll 8
        for (int k = 0; k < 64; k++) {
            float w = ws[h * 65 + k];
            #pragma unroll
            for (int i = 0; i < 8; i++)
                acc[i] = fmaf(xs[(rg * 8 + i) * 64 + k], w, acc[i]);
        }
    }
    float bias = dt_bias[h];
    #pragma unroll
    for (int i = 0; i < 8; i++) {
        float raw = acc[i] + bias;
        float sg = 1.f / (1.f + __expf(-raw));
        g_dt[(size_t)(bl0 + rg * 8 + i) * NHEADS + h] = DTMIN + (DTMAX - DTMIN) * sg;
    }
}

// ---------------- conv1d (K=4, causal) + bias + SiLU, 8 channels/thread, fp16 io ------
#define CD8 (CDIM / 8)   // 288
struct F8 { float v[8]; };
__device__ __forceinline__ F8 cvt8(uint4 u) {
    F8 r;
    __half2 h0 = *(__half2*)&u.x, h1 = *(__half2*)&u.y;
    __half2 h2 = *(__half2*)&u.z, h3 = *(__half2*)&u.w;
    r.v[0] = __low2float(h0); r.v[1] = __high2float(h0);
    r.v[2] = __low2float(h1); r.v[3] = __high2float(h1);
    r.v[4] = __low2float(h2); r.v[5] = __high2float(h2);
    r.v[6] = __low2float(h3); r.v[7] = __high2float(h3);
    return r;
}
__global__ void k_conv(const float* __restrict__ conv_w, const float* __restrict__ conv_b) {
    int idx = blockIdx.x * blockDim.x + threadIdx.x;
    if (idx >= BL * CD8) return;
    int c8 = (idx % CD8) * 8;
    int bl = idx / CD8;
    int l  = bl & (SEQ - 1);
    uint4 zu = make_uint4(0, 0, 0, 0);
    uint4 u3 = *(const uint4*)&g_zx_h[(size_t)bl * NIN + DINNER + c8];
    uint4 u2 = (l >= 1) ? *(const uint4*)&g_zx_h[(size_t)(bl - 1) * NIN + DINNER + c8] : zu;
    uint4 u1 = (l >= 2) ? *(const uint4*)&g_zx_h[(size_t)(bl - 2) * NIN + DINNER + c8] : zu;
    uint4 u0 = (l >= 3) ? *(const uint4*)&g_zx_h[(size_t)(bl - 3) * NIN + DINNER + c8] : zu;
    F8 v3 = cvt8(u3), v2 = cvt8(u2), v1 = cvt8(u1), v0 = cvt8(u0);
    float r[8];
    #pragma unroll
    for (int j = 0; j < 8; j++) {
        float4 w = *(const float4*)&conv_w[(c8 + j) * 4];
        float acc = conv_b[c8 + j];
        acc += v0.v[j] * w.x + v1.v[j] * w.y + v2.v[j] * w.z + v3.v[j] * w.w;
        r[j] = silu(acc);
    }
    uint4 out;
    *(__half2*)&out.x = __floats2half2_rn(r[0], r[1]);
    *(__half2*)&out.y = __floats2half2_rn(r[2], r[3]);
    *(__half2*)&out.z = __floats2half2_rn(r[4], r[5]);
    *(__half2*)&out.w = __floats2half2_rn(r[6], r[7]);
    *(uint4*)&g_xbc_h[(size_t)bl * CDIM + c8] = out;
}

// ---------------- head-independent CB[q][s] = C_q . B_s via HMMA (fp16 out) -----------
#define BSH 136    // stride in halves (272 B rows)

__global__ void __launch_bounds__(256) k_cb() {
    __shared__ __half Bh[64 * BSH];
    __shared__ __half Ch[64 * BSH];
    const int tid = threadIdx.x;
    const int bc = blockIdx.x;
    const int b  = bc / NCH, cc = bc % NCH;
    const long long base_bl = (long long)b * SEQ + (long long)cc * QC;

    #pragma unroll
    for (int it = 0; it < 8; it++) {
        int i4 = tid + it * 256;
        int q = i4 >> 5, n4 = (i4 & 31) * 4;
        *(uint2*)&Bh[q * BSH + n4] = *(const uint2*)&g_xbc_h[(base_bl + q) * CDIM + DINNER + n4];
        *(uint2*)&Ch[q * BSH + n4] = *(const uint2*)&g_xbc_h[(base_bl + q) * CDIM + DINNER + DSTATE + n4];
    }
    __syncthreads();

    const int w = tid >> 5, lid = tid & 31;
    const int m0 = (w >> 1) * 16;       // q tile
    const int nb = (w & 1) * 32;        // s base
    const uint32_t cbm = smem_u32(Ch), bbm = smem_u32(Bh);

    float acc[4][4];
    #pragma unroll
    for (int i = 0; i < 4; i++)
        #pragma unroll
        for (int j = 0; j < 4; j++) acc[i][j] = 0.f;

    const uint32_t a_base = cbm + (uint32_t)((m0 + (lid & 15)) * BSH + (lid >> 4) * 8) * 2;
    const int brow = lid & 7;
    const int bcol = ((lid >> 3) & 1) * 8;
    #pragma unroll
    for (int ks = 0; ks < 8; ks++) {
        uint32_t a[4];
        ldm_x4(a, a_base + ks * 32);
        #pragma unroll
        for (int ni = 0; ni < 4; ni++) {
            uint32_t bf[2];
            ldm_x2(bf, bbm + (uint32_t)((nb + ni * 8 + brow) * BSH + ks * 16 + bcol) * 2);
            mma_f16(acc[ni], a, bf);
        }
    }

    int q = m0 + (lid >> 2), s0 = nb + (lid & 3) * 2;
    size_t obase = (size_t)bc * (QC * QC);
    #pragma unroll
    for (int ni = 0; ni < 4; ni++) {
        *(__half2*)&g_CB_h[obase + (size_t)q * QC + s0 + ni * 8] =
            __floats2half2_rn(acc[ni][0], acc[ni][1]);
        *(__half2*)&g_CB_h[obase + (size_t)(q + 8) * QC + s0 + ni * 8] =
            __floats2half2_rn(acc[ni][2], acc[ni][3]);
    }
}

// ---------------- per-chunk per-head via HMMA: Yd + states ----------------
#define XSH 72     // 144 B rows

__global__ void __launch_bounds__(256) k_chunk(const float* __restrict__ A_log) {
    __shared__ __half xsh[64 * XSH];    // x tile [q][p]
    __shared__ __half Bsh[64 * BSH];    // ws-scaled B tile [q][n]
    __shared__ __half CBLh[64 * XSH];   // masked/scaled CB [q][s]
    __shared__ float dt_s[64], Ac_s[64], ws_s[64];

    const int tid = threadIdx.x;
    const int bc = blockIdx.x, h = blockIdx.y;
    const int b = bc / NCH, cc = bc % NCH;
    const long long base_bl = (long long)b * SEQ + (long long)cc * QC;

    // x tile: direct fp16 copy
    #pragma unroll
    for (int it = 0; it < 4; it++) {
        int i4 = tid + it * 256;
        int q = i4 >> 4, p4 = (i4 & 15) * 4;
        *(uint2*)&xsh[q * XSH + p4] = *(const uint2*)&g_xbc_h[(base_bl + q) * CDIM + h * HDIM + p4];
    }
    // stage B tile in regs (fp16, scaled by ws later)
    uint2 breg[8];
    #pragma unroll
    for (int it = 0; it < 8; it++) {
        int i4 = tid + it * 256;
        int q = i4 >> 5, n4 = (i4 & 31) * 4;
        breg[it] = *(const uint2*)&g_xbc_h[(base_bl + q) * CDIM + DINNER + n4];
    }
    if (tid < QC) dt_s[tid] = g_dt[(base_bl + tid) * NHEADS + h];
    __syncthreads();

    if (tid == 0) {
        float Ah = -__expf(A_log[h]);
        float s = 0.f;
        for (int q = 0; q < QC; q++) { s += dt_s[q] * Ah; Ac_s[q] = s; }
    }
    __syncthreads();

    if (tid < QC) {
        float last = Ac_s[QC - 1];
        ws_s[tid] = __expf(last - Ac_s[tid]) * dt_s[tid];
        g_Acum[((long long)bc * NHEADS + h) * QC + tid] = Ac_s[tid];
        if (tid == 0) g_cdecay[(long long)bc * NHEADS + h] = __expf(last);
    }
    // CBL -> fp16 (needs Ac_s, dt_s)
    #pragma unroll
    for (int it = 0; it < 4; it++) {
        int i4 = tid + it * 256;
        int q = i4 >> 4, s4 = (i4 & 15) * 4;
        __half2 cb01 = *(const __half2*)&g_CB_h[(size_t)bc * (QC * QC) + q * QC + s4];
        __half2 cb23 = *(const __half2*)&g_CB_h[(size_t)bc * (QC * QC) + q * QC + s4 + 2];
        float eq = Ac_s[q];
        float v0 = (s4 + 0 <= q) ? __low2float(cb01)  * __expf(eq - Ac_s[s4 + 0]) * dt_s[s4 + 0] : 0.f;
        float v1 = (s4 + 1 <= q) ? __high2float(cb01) * __expf(eq - Ac_s[s4 + 1]) * dt_s[s4 + 1] : 0.f;
        float v2 = (s4 + 2 <= q) ? __low2float(cb23)  * __expf(eq - Ac_s[s4 + 2]) * dt_s[s4 + 2] : 0.f;
        float v3 = (s4 + 3 <= q) ? __high2float(cb23) * __expf(eq - Ac_s[s4 + 3]) * dt_s[s4 + 3] : 0.f;
        *(__half2*)&CBLh[q * XSH + s4]     = __floats2half2_rn(v0, v1);
        *(__half2*)&CBLh[q * XSH + s4 + 2] = __floats2half2_rn(v2, v3);
    }
    __syncthreads();   // ws_s visible

    // Bsh = ws[q] * B[q][n] -> fp16
    #pragma unroll
    for (int it = 0; it < 8; it++) {
        int i4 = tid + it * 256;
        int q = i4 >> 5, n4 = (i4 & 31) * 4;
        float w = ws_s[q];
        __half2 b01 = *(__half2*)&breg[it].x;
        __half2 b23 = *(__half2*)&breg[it].y;
        *(__half2*)&Bsh[q * BSH + n4]     = __floats2half2_rn(__low2float(b01) * w, __high2float(b01) * w);
        *(__half2*)&Bsh[q * BSH + n4 + 2] = __floats2half2_rn(__low2float(b23) * w, __high2float(b23) * w);
    }
    __syncthreads();

    const int w = tid >> 5, lid = tid & 31;
    const uint32_t xb = smem_u32(xsh), cbb = smem_u32(CBLh), bbb = smem_u32(Bsh);

    // ---- Yd[q][p] = CBL x xs : A = CBLh row-major, B = xsh ([s][p]) via trans
    {
        const int m0 = (w >> 1) * 16;
        const int nb = (w & 1) * 32;
        float acc[4][4];
        #pragma unroll
        for (int i = 0; i < 4; i++)
            #pragma unroll
            for (int j = 0; j < 4; j++) acc[i][j] = 0.f;
        const uint32_t a_base = cbb + (uint32_t)((m0 + (lid & 15)) * XSH + (lid >> 4) * 8) * 2;
        const int bk = (lid & 7) + ((lid >> 3) & 1) * 8;
        #pragma unroll
        for (int ks = 0; ks < 4; ks++) {
            uint32_t a[4];
            ldm_x4(a, a_base + ks * 32);
            #pragma unroll
            for (int ni = 0; ni < 4; ni++) {
                uint32_t bf[2];
                ldm_x2_t(bf, xb + (uint32_t)((ks * 16 + bk) * XSH + nb + ni * 8) * 2);
                mma_f16(acc[ni], a, bf);
            }
        }
        int q = m0 + (lid >> 2), p0 = nb + (lid & 3) * 2;
        #pragma unroll
        for (int ni = 0; ni < 4; ni++) {
            *(float2*)&g_Y[(base_bl + q) * DINNER + h * HDIM + p0 + ni * 8] =
                make_float2(acc[ni][0], acc[ni][1]);
            *(float2*)&g_Y[(base_bl + q + 8) * DINNER + h * HDIM + p0 + ni * 8] =
                make_float2(acc[ni][2], acc[ni][3]);
        }
    }

    // ---- states[p][n] = (x.ws)^T x B : A = xsh trans ([q][p]), B = Bsh trans ([q][n])
    {
        const int m0 = (w >> 1) * 16;       // p tile
        const int nb = (w & 1) * 64;        // n base
        float acc[8][4];
        #pragma unroll
        for (int i = 0; i < 8; i++)
            #pragma unroll
            for (int j = 0; j < 4; j++) acc[i][j] = 0.f;
        const int ak = (lid & 7) + ((lid >> 4) & 1) * 8;
        const int am = m0 + ((lid >> 3) & 1) * 8;
        const int bk = (lid & 7) + ((lid >> 3) & 1) * 8;
        #pragma unroll
        for (int ks = 0; ks < 4; ks++) {
            uint32_t a[4];
            ldm_x4_t(a, xb + (uint32_t)((ks * 16 + ak) * XSH + am) * 2);
            #pragma unroll
            for (int ni = 0; ni < 8; ni++) {
                uint32_t bf[2];
                ldm_x2_t(bf, bbb + (uint32_t)((ks * 16 + bk) * BSH + nb + ni * 8) * 2);
                mma_f16(acc[ni], a, bf);
            }
        }
        long long sbase = ((long long)bc * NHEADS + h) * HDIM * DSTATE;
        int p = m0 + (lid >> 2), n0 = nb + (lid & 3) * 2;
        #pragma unroll
        for (int ni = 0; ni < 8; ni++) {
            *(__half2*)&g_states_h[sbase + (long long)p * DSTATE + n0 + ni * 8] =
                __floats2half2_rn(acc[ni][0], acc[ni][1]);
            *(__half2*)&g_states_h[sbase + (long long)(p + 8) * DSTATE + n0 + ni * 8] =
                __floats2half2_rn(acc[ni][2], acc[ni][3]);
        }
    }
}

// ---------------- parallel inter-chunk scan (half2 per thread, prefetch) --------------
__global__ void k_scan() {
    int el2 = blockIdx.x * 256 + threadIdx.x;
    int bh = el2 >> 12;
    int idx2 = (el2 & 4095) * 2;
    int b = bh >> 5, h = bh & 31;
    float cx = 0.f, cy = 0.f;
    long long bcn = (long long)b * NCH * NHEADS + h;
    __half2 st = *(const __half2*)&g_states_h[bcn * (HDIM * DSTATE) + idx2];
    float dec = g_cdecay[bcn];
    for (int c = 0; c < NCH; c++) {
        long long bcn_n = bcn + NHEADS;
        __half2 st_n = st;
        float dec_n = dec;
        if (c + 1 < NCH) {
            st_n = *(const __half2*)&g_states_h[bcn_n * (HDIM * DSTATE) + idx2];
            dec_n = g_cdecay[bcn_n];
        }
        *(__half2*)&g_prevs_h[bcn * (HDIM * DSTATE) + idx2] = __floats2half2_rn(cx, cy);
        cx = fmaf(dec, cx, __low2float(st));
        cy = fmaf(dec, cy, __high2float(st));
        st = st_n; dec = dec_n; bcn = bcn_n;
    }
}

// ---------------- Yo via HMMA + D_skip*x, accumulate into g_Y ----------------
__global__ void __launch_bounds__(256) k_yo(const float* __restrict__ D_skip) {
    __shared__ __half Csh[64 * BSH];   // C tile [q][n]
    __shared__ __half Pvh[64 * BSH];   // prevs [p][n]
    __shared__ float eA[64];

    const int tid = threadIdx.x;
    const int bc = blockIdx.x, h = blockIdx.y;
    const int b = bc / NCH, cc = bc % NCH;
    const long long base_bl = (long long)b * SEQ + (long long)cc * QC;
    const long long pbase = ((long long)bc * NHEADS + h) * (HDIM * DSTATE);

    #pragma unroll
    for (int it = 0; it < 8; it++) {
        int i4 = tid + it * 256;
        int r = i4 >> 5, n4 = (i4 & 31) * 4;
        *(uint2*)&Csh[r * BSH + n4] = *(const uint2*)&g_xbc_h[(base_bl + r) * CDIM + DINNER + DSTATE + n4];
        *(uint2*)&Pvh[r * BSH + n4] = *(const uint2*)&g_prevs_h[pbase + (long long)r * DSTATE + n4];
    }
    if (tid < QC) eA[tid] = __expf(g_Acum[((long long)bc * NHEADS + h) * QC + tid]);
    __syncthreads();

    const float dsk = D_skip[h];
    const int w = tid >> 5, lid = tid & 31;
    const int m0 = (w >> 1) * 16;       // q tile
    const int nb = (w & 1) * 32;        // p base
    const uint32_t cbm = smem_u32(Csh), pbm = smem_u32(Pvh);

    float acc[4][4];
    #pragma unroll
    for (int i = 0; i < 4; i++)
        #pragma unroll
        for (int j = 0; j < 4; j++) acc[i][j] = 0.f;

    const uint32_t a_base = cbm + (uint32_t)((m0 + (lid & 15)) * BSH + (lid >> 4) * 8) * 2;
    const int brow = lid & 7;
    const int bcol = ((lid >> 3) & 1) * 8;
    #pragma unroll
    for (int ks = 0; ks < 8; ks++) {
        uint32_t a[4];
        ldm_x4(a, a_base + ks * 32);
        #pragma unroll
        for (int ni = 0; ni < 4; ni++) {
            uint32_t bf[2];
            ldm_x2(bf, pbm + (uint32_t)((nb + ni * 8 + brow) * BSH + ks * 16 + bcol) * 2);
            mma_f16(acc[ni], a, bf);
        }
    }

    int q = m0 + (lid >> 2), p0 = nb + (lid & 3) * 2;
    float e0 = eA[q], e1 = eA[q + 8];
    #pragma unroll
    for (int ni = 0; ni < 4; ni++) {
        int p = p0 + ni * 8;
        long long r0 = base_bl + q, r1 = base_bl + q + 8;
        float2 y0 = *(float2*)&g_Y[r0 * DINNER + h * HDIM + p];
        __half2 xh0 = *(const __half2*)&g_xbc_h[r0 * CDIM + h * HDIM + p];
        y0.x += e0 * acc[ni][0] + dsk * __low2float(xh0);
        y0.y += e0 * acc[ni][1] + dsk * __high2float(xh0);
        *(float2*)&g_Y[r0 * DINNER + h * HDIM + p] = y0;
        float2 y1 = *(float2*)&g_Y[r1 * DINNER + h * HDIM + p];
        __half2 xh1 = *(const __half2*)&g_xbc_h[r1 * CDIM + h * HDIM + p];
        y1.x += e1 * acc[ni][2] + dsk * __low2float(xh1);
        y1.y += e1 * acc[ni][3] + dsk * __high2float(xh1);
        *(float2*)&g_Y[r1 * DINNER + h * HDIM + p] = y1;
    }
}

// ---------------- gate with silu(z) + RMSNorm (vectorized), emit fp16 ----------------
__global__ void k_gate(const float* __restrict__ norm_w) {
    const long long row = blockIdx.x;
    const int t = threadIdx.x;                  // 256 threads, 8 elems each
    float v[8];
    float local = 0.f;
    #pragma unroll
    for (int j = 0; j < 2; j++) {
        int i = (t + j * 256) * 4;
        float4 yv = *(const float4*)&g_Y[row * DINNER + i];
        uint2 zu = *(const uint2*)&g_zx_h[row * NIN + i];
        __half2 z01 = *(__half2*)&zu.x, z23 = *(__half2*)&zu.y;
        v[j*4+0] = yv.x * silu(__low2float(z01));
        v[j*4+1] = yv.y * silu(__high2float(z01));
        v[j*4+2] = yv.z * silu(__low2float(z23));
        v[j*4+3] = yv.w * silu(__high2float(z23));
        local += v[j*4+0]*v[j*4+0] + v[j*4+1]*v[j*4+1] + v[j*4+2]*v[j*4+2] + v[j*4+3]*v[j*4+3];
    }
    float tot = block_sum(local);
    float scale = rsqrtf(tot / DINNER + 1e-5f);
    #pragma unroll
    for (int j = 0; j < 2; j++) {
        int i = (t + j * 256) * 4;
        float4 nw = *(const float4*)&norm_w[i];
        *(__half2*)&g_y_h[row * DINNER + i]     = __floats2half2_rn(v[j*4+0] * scale * nw.x, v[j*4+1] * scale * nw.y);
        *(__half2*)&g_y_h[row * DINNER + i + 2] = __floats2half2_rn(v[j*4+2] * scale * nw.z, v[j*4+3] * scale * nw.w);
    }
}

// ---------------- final LayerNorm + residual ----------------
__global__ void k_ln(const float* __restrict__ x, const float* __restrict__ ln_w,
                     const float* __restrict__ ln_b, float* __restrict__ out) {
    const long long row = blockIdx.x;
    const int t = threadIdx.x;
    float4 o = ((const float4*)&g_out[row * DMODEL])[t];
    float s = o.x + o.y + o.z + o.w;
    float sq = o.x*o.x + o.y*o.y + o.z*o.z + o.w*o.w;
    float sum = block_sum(s);
    float sumsq = block_sum(sq);
    float mu = sum / DMODEL;
    float var = sumsq / DMODEL - mu * mu;
    float rs = rsqrtf(var + 1e-5f);
    float4 xr = ((const float4*)&x[row * DMODEL])[t];
    float4 w = ((const float4*)ln_w)[t];
    float4 bb = ((const float4*)ln_b)[t];
    float4 r;
    r.x = xr.x + (o.x - mu) * rs * w.x + bb.x;
    r.y = xr.y + (o.y - mu) * rs * w.y + bb.y;
    r.z = xr.z + (o.z - mu) * rs * w.z + bb.z;
    r.w = xr.w + (o.w - mu) * rs * w.w + bb.w;
    ((float4*)&out[row * DMODEL])[t] = r;
}

// ---------------- launch ----------------
extern "C" void kernel_launch(void* const* d_in, const int* in_sizes, int n_in,
                              void* d_out, int out_size) {
    const float* x          = (const float*)d_in[0];
    const float* in_proj_w  = (const float*)d_in[1];
    const float* conv_w     = (const float*)d_in[2];
    const float* conv_b     = (const float*)d_in[3];
    const float* dt_bias    = (const float*)d_in[4];
    const float* A_log      = (const float*)d_in[5];
    const float* D_skip     = (const float*)d_in[6];
    const float* norm_w     = (const float*)d_in[7];
    const float* out_proj_w = (const float*)d_in[8];
    const float* ln_w       = (const float*)d_in[9];
    const float* ln_b       = (const float*)d_in[10];
    float* out = (float*)d_out;
    (void)in_sizes; (void)n_in; (void)out_size;

    cudaFuncSetAttribute(k_gemm_h<__half>, cudaFuncAttributeMaxDynamicSharedMemorySize,
                         GEMMH_SMEM_BYTES);
    cudaFuncSetAttribute(k_gemm_h<float>, cudaFuncAttributeMaxDynamicSharedMemorySize,
                         GEMMH_SMEM_BYTES);

    __half *xh, *w1h, *yh, *w2h, *zxh;
    float *go;
    cudaGetSymbolAddress((void**)&xh,  g_x_h);
    cudaGetSymbolAddress((void**)&w1h, g_w1_h);
    cudaGetSymbolAddress((void**)&yh,  g_y_h);
    cudaGetSymbolAddress((void**)&w2h, g_w2_h);
    cudaGetSymbolAddress((void**)&zxh, g_zx_h);
    cudaGetSymbolAddress((void**)&go,  g_out);

    // 0) fp16 conversions
    k_cvt_h<<<(int)(((long long)BL * DMODEL / 4 + 255) / 256), 256>>>(x, xh, (long long)BL * DMODEL / 4);
    k_cvt_h<<<(int)(((long long)NIN * DMODEL / 4 + 255) / 256), 256>>>(in_proj_w, w1h, (long long)NIN * DMODEL / 4);
    k_cvt_h<<<(int)(((long long)DMODEL * DINNER / 4 + 255) / 256), 256>>>(out_proj_w, w2h, (long long)DMODEL * DINNER / 4);

    // 1) in_proj GEMM (fp16 HMMA, 3-stage, fp16 out)
    k_gemm_h<__half><<<dim3((NIN + 127) / 128, BL / 128), 256, GEMMH_SMEM_BYTES>>>(
        xh, w1h, zxh, BL, NIN, DMODEL);
    // 2) causal conv + SiLU (fp16 io)
    k_conv<<<(BL * CD8 + 255) / 256, 256>>>(conv_w, conv_b);
    // 3) fp32-exact dt
    k_dtfix<<<BL / 64, 256>>>(x, in_proj_w, dt_bias);
    // 4a) head-independent CB (HMMA, fp16 out)
    k_cb<<<BATCH * NCH, 256>>>();
    // 4b) per-chunk per-head work (HMMA)
    k_chunk<<<dim3(BATCH * NCH, NHEADS), 256>>>(A_log);
    // 5) inter-chunk scan
    k_scan<<<(BATCH * NHEADS * HDIM * DSTATE / 2) / 256, 256>>>();
    // 6) Yo + skip (HMMA)
    k_yo<<<dim3(BATCH * NCH, NHEADS), 256>>>(D_skip);
    // 7) gate + rmsnorm (vectorized, emits fp16)
    k_gate<<<BL, 256>>>(norm_w);
    // 8) out_proj GEMM (fp16 HMMA, 3-stage, fp32 out)
    k_gemm_h<float><<<dim3(DMODEL / 128, BL / 128), 256, GEMMH_SMEM_BYTES>>>(
        yh, w2h, go, BL, DMODEL, DINNER);
    // 9) LayerNorm + residual
    k_ln<<<BL, 256>>>(x, ln_w, ln_b, out);
}